// round 2
// baseline (speedup 1.0000x reference)
#include <cuda_runtime.h>

#define BB 8
#define NQV 4096
#define NKV 4096
#define CC 256
#define KNN 16
#define HH 32
#define EPSV 1e-5f

// Scratch (device globals: allocation-free rule)
__device__ float    g_kvproj[BB * NKV * HH];   // s1 * (kv_feat @ w1a^T)
__device__ float    g_qterm [BB * NQV * HH];   // s1 * (q_feat @ (w1b-w1a)^T) + t1
__device__ unsigned g_topk  [BB * NQV * KNN];  // neighbor indices (unordered set)

// ---------------------------------------------------------------------------
// Kernel A: projection GEMM. out[row][h] = sum_c feat[row][c] * W(h,c)
//   mode 0: W = w1[h][c]            -> g_kvproj, epilogue *= s1[h]
//   mode 1: W = w1[h][C+c]-w1[h][c] -> g_qterm,  epilogue = acc*s1[h] + t1[h]
// ---------------------------------------------------------------------------
__global__ __launch_bounds__(256) void proj_kernel(
    const float* __restrict__ feat, const float* __restrict__ w1,
    const float* __restrict__ g1, const float* __restrict__ b1,
    const float* __restrict__ m1, const float* __restrict__ v1, int mode)
{
    __shared__ float AsubT[32][132];  // [k][m], padded
    __shared__ float WT[32][36];      // [k][h], padded

    const int tid  = threadIdx.x;
    const int row0 = blockIdx.x * 128;
    const int h0   = (tid & 7) * 4;
    const int m0   = (tid >> 3) * 4;

    float acc[4][4];
#pragma unroll
    for (int i = 0; i < 4; ++i)
#pragma unroll
        for (int j = 0; j < 4; ++j) acc[i][j] = 0.0f;

    for (int k0 = 0; k0 < CC; k0 += 32) {
        {
            const int q4 = (tid & 7) * 4;
            const int r  = tid >> 3;
#pragma unroll
            for (int j = 0; j < 4; ++j) {
                const int row = r + j * 32;
                const float4 v = *(const float4*)(feat + (size_t)(row0 + row) * CC + k0 + q4);
                AsubT[q4 + 0][row] = v.x;
                AsubT[q4 + 1][row] = v.y;
                AsubT[q4 + 2][row] = v.z;
                AsubT[q4 + 3][row] = v.w;
            }
        }
        {
            const int kk = tid & 31;
            const int hb = tid >> 5;
#pragma unroll
            for (int j = 0; j < 4; ++j) {
                const int hh = hb + j * 8;
                float w = w1[hh * (2 * CC) + k0 + kk];
                if (mode) w = w1[hh * (2 * CC) + CC + k0 + kk] - w;
                WT[kk][hh] = w;
            }
        }
        __syncthreads();
#pragma unroll
        for (int kk = 0; kk < 32; ++kk) {
            const float4 a = *(const float4*)&AsubT[kk][m0];
            const float4 w = *(const float4*)&WT[kk][h0];
            const float av[4] = {a.x, a.y, a.z, a.w};
            const float wv[4] = {w.x, w.y, w.z, w.w};
#pragma unroll
            for (int i = 0; i < 4; ++i)
#pragma unroll
                for (int j = 0; j < 4; ++j)
                    acc[i][j] = fmaf(av[i], wv[j], acc[i][j]);
        }
        __syncthreads();
    }

    float sv[4], tv[4];
#pragma unroll
    for (int j = 0; j < 4; ++j) {
        const int h = h0 + j;
        const float sc = g1[h] * rsqrtf(v1[h] + EPSV);
        sv[j] = sc;
        tv[j] = mode ? (b1[h] - m1[h] * sc) : 0.0f;
    }
    float* out = mode ? g_qterm : g_kvproj;
#pragma unroll
    for (int i = 0; i < 4; ++i) {
        float4 o;
        o.x = fmaf(acc[i][0], sv[0], tv[0]);
        o.y = fmaf(acc[i][1], sv[1], tv[1]);
        o.z = fmaf(acc[i][2], sv[2], tv[2]);
        o.w = fmaf(acc[i][3], sv[3], tv[3]);
        *(float4*)(out + (size_t)(row0 + m0 + i) * HH + h0) = o;
    }
}

// ---------------------------------------------------------------------------
// Kernel B: exact top-16 nearest neighbors. One QUERY PER LANE.
// Pass 1: maintain 16 smallest exact f32 distances (sorted FMNMX chain).
// Pass 2: tau = 16th smallest; emit first 16 indices with d <= tau
//         (index order == top_k stable tie-break; set order is irrelevant
//          downstream because the K-reduction is max).
// Candidates staged in smem as float4 {x,y,z,|k|^2}, broadcast to all lanes.
// ---------------------------------------------------------------------------
extern "C" __global__ __launch_bounds__(256) void topk_kernel(
    const float* __restrict__ qxyz, const float* __restrict__ kxyz)
{
    extern __shared__ float4 s_pts[];  // 4096 x 16B = 64KB
    const int tid = threadIdx.x;
    const int b   = blockIdx.x >> 4;           // 16 blocks per batch
    const int q   = b * NQV + (blockIdx.x & 15) * 256 + tid;

    const float* kb = kxyz + (size_t)b * NKV * 3;
    for (int i = tid; i < NKV; i += 256) {
        const float x = kb[i * 3 + 0];
        const float y = kb[i * 3 + 1];
        const float z = kb[i * 3 + 2];
        s_pts[i] = make_float4(x, y, z, x * x + y * y + z * z);
    }
    __syncthreads();

    const float qx = qxyz[(size_t)q * 3 + 0];
    const float qy = qxyz[(size_t)q * 3 + 1];
    const float qz = qxyz[(size_t)q * 3 + 2];
    const float ax = -2.0f * qx, ay = -2.0f * qy, az = -2.0f * qz;
    const float qn = qx * qx + qy * qy + qz * qz;

    float s[16];
#pragma unroll
    for (int j = 0; j < 16; ++j) s[j] = 3.402823466e38f;

    // Pass 1: exact top-16 distances
    for (int t = 0; t < NKV; t += 4) {
        float d[4];
#pragma unroll
        for (int u = 0; u < 4; ++u) {
            const float4 p = s_pts[t + u];
            float dd = fmaf(ax, p.x, qn + p.w);
            dd = fmaf(ay, p.y, dd);
            dd = fmaf(az, p.z, dd);
            d[u] = dd;
        }
#pragma unroll
        for (int u = 0; u < 4; ++u) {
            float dd = d[u];
            if (dd < s[15]) {   // divergent branch; chain is identity for
                                // lanes whose dd doesn't qualify
#pragma unroll
                for (int j = 0; j < 16; ++j) {
                    const float lo = fminf(dd, s[j]);
                    dd = fmaxf(dd, s[j]);
                    s[j] = lo;
                }
            }
        }
    }

    // Pass 2: recover indices. d <= tau, first 16 in index order.
    const float tau = s[15];
    unsigned* o = g_topk + (size_t)q * KNN;
    int cnt = 0;
    for (int t = 0; t < NKV; t += 4) {
#pragma unroll
        for (int u = 0; u < 4; ++u) {
            const float4 p = s_pts[t + u];
            float dd = fmaf(ax, p.x, qn + p.w);
            dd = fmaf(ay, p.y, dd);
            dd = fmaf(az, p.z, dd);
            if (dd <= tau && cnt < 16) {
                o[cnt] = (unsigned)(t + u);
                ++cnt;
            }
        }
    }
}

// ---------------------------------------------------------------------------
// Kernel C: gather + add + leaky + max over K, then y = max @ w2^T + BN2 + leaky
// ---------------------------------------------------------------------------
__global__ __launch_bounds__(256) void fuse_kernel(
    const float* __restrict__ w2, const float* __restrict__ g2,
    const float* __restrict__ b2, const float* __restrict__ m2,
    const float* __restrict__ v2, float* __restrict__ out)
{
    __shared__ float w2t[HH][260];    // transposed w2, padded
    __shared__ float smaxT[HH][68];   // [h][q_local]
    __shared__ float s2s[CC], t2s[CC];

    const int tid = threadIdx.x;

    for (int idx = tid; idx < CC * HH; idx += 256) {
        const int c = idx >> 5, h = idx & 31;
        w2t[h][c] = w2[idx];
    }
    {
        const float sc = g2[tid] * rsqrtf(v2[tid] + EPSV);
        s2s[tid] = sc;
        t2s[tid] = b2[tid] - m2[tid] * sc;
    }

    const int r0   = blockIdx.x * 64;
    const int b    = r0 >> 12;
    const int warp = tid >> 5, lane = tid & 31;
    const float* kvb = g_kvproj + (size_t)b * NKV * HH;

    for (int qi = warp * 8; qi < warp * 8 + 8; ++qi) {
        const int r = r0 + qi;
        const float qt = g_qterm[(size_t)r * HH + lane];
        const uint4* ip = (const uint4*)(g_topk + (size_t)r * KNN);
        const uint4 i0 = ip[0], i1 = ip[1], i2 = ip[2], i3 = ip[3];
        const unsigned id[16] = {i0.x, i0.y, i0.z, i0.w, i1.x, i1.y, i1.z, i1.w,
                                 i2.x, i2.y, i2.z, i2.w, i3.x, i3.y, i3.z, i3.w};
        float mx = -3.402823466e38f;
#pragma unroll
        for (int k = 0; k < 16; ++k) {
            float v = kvb[(size_t)id[k] * HH + lane] + qt;
            v = fmaxf(v, 0.2f * v);  // leaky relu (slope < 1)
            mx = fmaxf(mx, v);
        }
        smaxT[lane][qi] = mx;
    }
    __syncthreads();

    const int q0 = (tid & 15) * 4;
    const int c0 = (tid >> 4) * 16;
    float acc[4][16];
#pragma unroll
    for (int i = 0; i < 4; ++i)
#pragma unroll
        for (int j = 0; j < 16; ++j) acc[i][j] = 0.0f;

#pragma unroll 8
    for (int kk = 0; kk < HH; ++kk) {
        const float4 a = *(const float4*)&smaxT[kk][q0];
        const float av[4] = {a.x, a.y, a.z, a.w};
        float bv[16];
#pragma unroll
        for (int j4 = 0; j4 < 4; ++j4) {
            const float4 t = *(const float4*)&w2t[kk][c0 + j4 * 4];
            bv[j4 * 4 + 0] = t.x; bv[j4 * 4 + 1] = t.y;
            bv[j4 * 4 + 2] = t.z; bv[j4 * 4 + 3] = t.w;
        }
#pragma unroll
        for (int i = 0; i < 4; ++i)
#pragma unroll
            for (int j = 0; j < 16; ++j)
                acc[i][j] = fmaf(av[i], bv[j], acc[i][j]);
    }

#pragma unroll
    for (int i = 0; i < 4; ++i) {
        const int r = r0 + q0 + i;
        float* op = out + (size_t)r * CC + c0;
#pragma unroll
        for (int j4 = 0; j4 < 4; ++j4) {
            float4 o;
            float y;
            y = fmaf(acc[i][j4 * 4 + 0], s2s[c0 + j4 * 4 + 0], t2s[c0 + j4 * 4 + 0]); o.x = fmaxf(y, 0.2f * y);
            y = fmaf(acc[i][j4 * 4 + 1], s2s[c0 + j4 * 4 + 1], t2s[c0 + j4 * 4 + 1]); o.y = fmaxf(y, 0.2f * y);
            y = fmaf(acc[i][j4 * 4 + 2], s2s[c0 + j4 * 4 + 2], t2s[c0 + j4 * 4 + 2]); o.z = fmaxf(y, 0.2f * y);
            y = fmaf(acc[i][j4 * 4 + 3], s2s[c0 + j4 * 4 + 3], t2s[c0 + j4 * 4 + 3]); o.w = fmaxf(y, 0.2f * y);
            *(float4*)(op + j4 * 4) = o;
        }
    }
}

// ---------------------------------------------------------------------------
extern "C" void kernel_launch(void* const* d_in, const int* in_sizes, int n_in,
                              void* d_out, int out_size)
{
    const float* qf   = (const float*)d_in[0];   // (8,4096,256)
    const float* qxyz = (const float*)d_in[1];   // (8,4096,3)
    const float* kvf  = (const float*)d_in[2];   // (8,4096,256)
    const float* kxyz = (const float*)d_in[3];   // (8,4096,3)
    const float* w1   = (const float*)d_in[4];   // (32,512)
    const float* g1   = (const float*)d_in[5];
    const float* b1   = (const float*)d_in[6];
    const float* m1   = (const float*)d_in[7];
    const float* v1   = (const float*)d_in[8];
    const float* w2   = (const float*)d_in[9];   // (256,32)
    const float* g2   = (const float*)d_in[10];
    const float* b2   = (const float*)d_in[11];
    const float* m2   = (const float*)d_in[12];
    const float* v2   = (const float*)d_in[13];
    float* out = (float*)d_out;

    cudaFuncSetAttribute(topk_kernel, cudaFuncAttributeMaxDynamicSharedMemorySize, 65536);

    proj_kernel<<<256, 256>>>(kvf, w1, g1, b1, m1, v1, 0);
    proj_kernel<<<256, 256>>>(qf,  w1, g1, b1, m1, v1, 1);
    topk_kernel<<<128, 256, 65536>>>(qxyz, kxyz);
    fuse_kernel<<<512, 256>>>(w2, g2, b2, m2, v2, out);
}